// round 9
// baseline (speedup 1.0000x reference)
#include <cuda_runtime.h>

#define H 512
#define W 512
#define B 64
#define RB 32
#define NSTRIPS (H / RB)   // 16
#define NT 256
#define NBLK (B * NSTRIPS) // 1024

typedef unsigned long long u64;

__device__ float g_part[NBLK * 3];
__device__ unsigned g_count;   // zero at load; last block resets each launch

// ---------- packed f32x2 helpers ----------
__device__ __forceinline__ u64 padd(u64 a, u64 b) {
    u64 r; asm("add.rn.f32x2 %0, %1, %2;" : "=l"(r) : "l"(a), "l"(b)); return r;
}
__device__ __forceinline__ u64 pmul(u64 a, u64 b) {
    u64 r; asm("mul.rn.f32x2 %0, %1, %2;" : "=l"(r) : "l"(a), "l"(b)); return r;
}
__device__ __forceinline__ u64 pfma(u64 a, u64 b, u64 c) {
    u64 r; asm("fma.rn.f32x2 %0, %1, %2, %3;" : "=l"(r) : "l"(a), "l"(b), "l"(c)); return r;
}
__device__ __forceinline__ u64 pdup(float x) {
    unsigned u = __float_as_uint(x);
    return ((u64)u << 32) | (u64)u;
}
#define NEG1_C 0xBF800000BF800000ULL
__device__ __forceinline__ u64 psub(u64 a, u64 b) { return pfma(b, (u64)NEG1_C, a); }
__device__ __forceinline__ u64 pabs(u64 a) { return a & 0x7FFFFFFF7FFFFFFFULL; }
__device__ __forceinline__ float plo(u64 a) { return __uint_as_float((unsigned)a); }
__device__ __forceinline__ float phi(u64 a) { return __uint_as_float((unsigned)(a >> 32)); }
__device__ __forceinline__ u64 ppack(float lo, float hi) {
    return ((u64)__float_as_uint(hi) << 32) | (u64)__float_as_uint(lo);
}

// Converted fields for one row, 2 cols per thread:
// ud = u_t - u_p, us = u_t + u_p, same for v.
struct F4 { u64 ud, us, vd, vs; };

__device__ __forceinline__ u64 ldu64(const float* __restrict__ rowbase, int t) {
    return *(reinterpret_cast<const u64*>(rowbase) + t);
}

__device__ __forceinline__ F4 ldconv(const float* __restrict__ pu,
                                     const float* __restrict__ pv,
                                     const float* __restrict__ tu,
                                     const float* __restrict__ tv,
                                     int y, int t) {
    const size_t off = (size_t)y * W;
    u64 qpu = ldu64(pu + off, t);
    u64 qpv = ldu64(pv + off, t);
    u64 qtu = ldu64(tu + off, t);
    u64 qtv = ldu64(tv + off, t);
    F4 f;
    f.ud = psub(qtu, qpu);
    f.us = padd(qtu, qpu);
    f.vd = psub(qtv, qpv);
    f.vs = padd(qtv, qpv);
    return f;
}

// Column-shifted pairs for a (d,s) field pair of one plane.
// Ad = (col-1, col0) of d; Cd = (col1, col+2) of d; same for s.
// Seam values converted from two scalar global loads (pred+trut).
__device__ __forceinline__ void shifts2(u64 cd, u64 cs,
                                        const float* __restrict__ pRow,
                                        const float* __restrict__ tRow,
                                        int tid, int lane,
                                        u64& Ad, u64& Cd, u64& As, u64& Cs) {
    float c0d = plo(cd), c1d = phi(cd);
    float c0s = plo(cs), c1s = phi(cs);
    bool pl = (lane == 0)  && (tid > 0);
    bool pr = (lane == 31) && (tid < NT - 1);
    float sd = 0.0f, ss = 0.0f;
    if (pl | pr) {
        int off = pl ? (2 * tid - 1) : (2 * tid + 2);
        float vp = __ldg(pRow + off);
        float vt = __ldg(tRow + off);
        sd = vt - vp;
        ss = vt + vp;
    }
    float Ldd = __shfl_up_sync(0xFFFFFFFFu, c1d, 1);
    float Lss = __shfl_up_sync(0xFFFFFFFFu, c1s, 1);
    float Rdd = __shfl_down_sync(0xFFFFFFFFu, c0d, 1);
    float Rss = __shfl_down_sync(0xFFFFFFFFu, c0s, 1);
    if (pl) { Ldd = sd; Lss = ss; }
    if (pr) { Rdd = sd; Rss = ss; }
    Ad = ppack(Ldd, c0d);
    Cd = ppack(c1d, Rdd);
    As = ppack(Lss, c0s);
    Cs = ppack(c1s, Rss);
}

__global__ __launch_bounds__(NT, 3) void loss_kernel(const float* __restrict__ pred,
                                                     const float* __restrict__ trut,
                                                     float* __restrict__ out)
{
    const int bx = blockIdx.x;
    const int img = bx >> 4;               // / NSTRIPS
    const int strip = bx & (NSTRIPS - 1);
    const int y0 = strip * RB;
    const int tid = threadIdx.x;
    const int lane = tid & 31;

    const size_t HW = (size_t)H * W;
    const float* __restrict__ pu = pred + (size_t)img * 2 * HW;
    const float* __restrict__ pv = pu + HW;
    const float* __restrict__ tu = trut + (size_t)img * 2 * HW;
    const float* __restrict__ tv = tu + HW;

    const u64 NEG8  = pdup(-8.0f);
    const u64 N8IRE = pdup(-8.0f * (1.0f / 400.0f));   // -0.02

    F4 prev = {0, 0, 0, 0};
    if (y0 > 0) prev = ldconv(pu, pv, tu, tv, y0 - 1, tid);
    F4 cur  = ldconv(pu, pv, tu, tv, y0, tid);
    F4 next = ldconv(pu, pv, tu, tv, y0 + 1, tid);

    u64 accM = 0, accO = 0, accL = 0;

    #pragma unroll 1
    for (int r = 0; r < RB; ++r) {
        const int y = y0 + r;

        // prefetch row y+2 at the top (consumed as 'next' at iteration r+1)
        F4 buf = {0, 0, 0, 0};
        const int yn = y + 2;
        if (r < RB - 1 && yn < H) buf = ldconv(pu, pv, tu, tv, yn, tid);

        // L1 on all points: |t - p| for both channels
        accL = padd(accL, padd(pabs(cur.ud), pabs(cur.vd)));

        if (y >= 1 && y <= H - 2) {
            const size_t roff = (size_t)y * W;
            u64 uAd, uCd, uAs, uCs, vAd, vCd, vAs, vCs;
            shifts2(cur.ud, cur.us, pu + roff, tu + roff, tid, lane, uAd, uCd, uAs, uCs);
            shifts2(cur.vd, cur.vs, pv + roff, tv + roff, tid, lane, vAd, vCd, vAs, vCs);

            // P-terms (stencil sums with center), d and s variants
            u64 P6d = padd(next.ud, cur.ud), P6s = padd(next.us, cur.us); // ur+um
            u64 P8d = padd(prev.ud, cur.ud), P8s = padd(prev.us, cur.us); // ul+um
            u64 P1d = padd(uCd, cur.ud),     P1s = padd(uCs, cur.us);     // ut+um
            u64 P3d = padd(uAd, cur.ud),     P3s = padd(uAs, cur.us);     // ub+um
            u64 P2d = padd(vCd, cur.vd),     P2s = padd(vCs, cur.vs);     // vt+vm
            u64 P4d = padd(vAd, cur.vd),     P4s = padd(vAs, cur.vs);     // vb+vm
            u64 P5d = padd(next.vd, cur.vd), P5s = padd(next.vs, cur.vs); // vr+vm
            u64 P7d = padd(prev.vd, cur.vd), P7s = padd(prev.vs, cur.vs); // vl+vm

            // mass diff (raw; *0.5 at finalize): (ur_d-ul_d)+(vt_d-vb_d)
            u64 mass = padd(psub(P6d, P8d), psub(P2d, P4d));
            accM = padd(accM, pabs(mass));

            // mom_u diff (raw; *0.125 at finalize):
            // 2(P6d P6s - P8d P8s) + (P1d P2s + P1s P2d - P3d P4s - P3s P4d)
            //   - 8*IRE*(P6d+P8d+P1d+P3d - 8 um_d)
            u64 A  = psub(pmul(P6d, P6s), pmul(P8d, P8s));
            u64 A2 = padd(A, A);
            u64 cr = psub(pfma(P1s, P2d, pmul(P1d, P2s)),
                          pfma(P3s, P4d, pmul(P3d, P4s)));
            u64 Xu = padd(A2, cr);
            u64 lu = pfma(cur.ud, NEG8, padd(padd(P6d, P8d), padd(P1d, P3d)));
            u64 momu = pfma(lu, N8IRE, Xu);

            // mom_v diff (raw; *0.125 at finalize)
            u64 Av  = psub(pmul(P2d, P2s), pmul(P4d, P4s));
            u64 Av2 = padd(Av, Av);
            u64 crv = psub(pfma(P5s, P6d, pmul(P5d, P6s)),
                           pfma(P7s, P8d, pmul(P7d, P8s)));
            u64 Xv = padd(Av2, crv);
            u64 lv = pfma(cur.vd, NEG8, padd(padd(P5d, P7d), padd(P2d, P4d)));
            u64 momv = pfma(lv, N8IRE, Xv);

            accO = padd(accO, padd(pabs(momu), pabs(momv)));
        }

        // rotate sliding window
        prev = cur; cur = next; next = buf;
    }

    // mask boundary columns 0 (lo of tid 0) and 511 (hi of tid NT-1)
    if (tid == 0)      { accM &= 0xFFFFFFFF00000000ULL; accO &= 0xFFFFFFFF00000000ULL; }
    if (tid == NT - 1) { accM &= 0x00000000FFFFFFFFULL; accO &= 0x00000000FFFFFFFFULL; }

    float sM = plo(accM) + phi(accM);
    float sO = plo(accO) + phi(accO);
    float sL = plo(accL) + phi(accL);

    // block reduce (8 warps)
    const unsigned FULL = 0xFFFFFFFFu;
    #pragma unroll
    for (int off = 16; off > 0; off >>= 1) {
        sM += __shfl_down_sync(FULL, sM, off);
        sO += __shfl_down_sync(FULL, sO, off);
        sL += __shfl_down_sync(FULL, sL, off);
    }
    __shared__ float sh[8][3];
    __shared__ int sh_last;
    const int wid = tid >> 5;
    if (lane == 0) { sh[wid][0] = sM; sh[wid][1] = sO; sh[wid][2] = sL; }
    __syncthreads();

    if (tid == 0) {
        float m = 0.f, o = 0.f, l = 0.f;
        #pragma unroll
        for (int i = 0; i < 8; ++i) { m += sh[i][0]; o += sh[i][1]; l += sh[i][2]; }
        g_part[bx * 3 + 0] = m;
        g_part[bx * 3 + 1] = o;
        g_part[bx * 3 + 2] = l;
        __threadfence();
        unsigned pc = atomicAdd(&g_count, 1u);
        sh_last = (pc == (unsigned)(NBLK - 1)) ? 1 : 0;
    }
    __syncthreads();

    // Last block reduces partials and writes the scalar.
    if (sh_last) {
        __threadfence();
        double dm = 0.0, dO = 0.0, dl = 0.0;
        for (int i = tid; i < NBLK; i += NT) {
            dm += (double)__ldcg(&g_part[i * 3 + 0]);
            dO += (double)__ldcg(&g_part[i * 3 + 1]);
            dl += (double)__ldcg(&g_part[i * 3 + 2]);
        }
        #pragma unroll
        for (int off = 16; off > 0; off >>= 1) {
            dm += __shfl_down_sync(FULL, dm, off);
            dO += __shfl_down_sync(FULL, dO, off);
            dl += __shfl_down_sync(FULL, dl, off);
        }
        __shared__ double shd[8][3];
        if (lane == 0) { shd[wid][0] = dm; shd[wid][1] = dO; shd[wid][2] = dl; }
        __syncthreads();
        if (tid == 0) {
            double m = 0.0, o = 0.0, l = 0.0;
            #pragma unroll
            for (int i = 0; i < 8; ++i) { m += shd[i][0]; o += shd[i][1]; l += shd[i][2]; }
            const double NM = (double)B * (H - 2) * (W - 2);
            const double NL = (double)B * 2.0 * H * W;
            double lossMass = 0.5   * m / NM;
            double lossMom  = 0.125 * o / NM;
            double lossL1   = l / NL;
            out[0] = (float)((lossMass * 5.0 + lossMom * 25.0 + lossL1) / 3.0);
            g_count = 0;   // reset for next graph replay
        }
    }
}

extern "C" void kernel_launch(void* const* d_in, const int* in_sizes, int n_in,
                              void* d_out, int out_size) {
    const float* pred = (const float*)d_in[0];
    const float* trut = (const float*)d_in[1];
    float* out = (float*)d_out;
    loss_kernel<<<NBLK, NT>>>(pred, trut, out);
}